// round 14
// baseline (speedup 1.0000x reference)
#include <cuda_runtime.h>
#include <cuda_fp16.h>
#include <cuda_bf16.h>
#include <cstdint>

// ---------------------------------------------------------------------------
// SCNLinkPredictor — fp16 mma.sync m16n8k16, BE=64, 2 CTAs/SM,
// per-warp-pair weight rings. R14: binary-search CN count with the
// saturation off-by-one FIXED (descent sums to 63; final probe extends to 64).
//
//  k0: fused [weight permute->fp16 | CN counts + compaction]
//  k1: fused CN-MLP table (layer2 + spin-barrier + layer3), 8 blocks
//  k2: main: 64 edges/CTA, 8 warps (2M x 4N). A row-major fp16 (stride 264).
//      B streamed per warp-pair: 4-deep 4KB ring, cp.async.wait_group +
//      bar.sync(pair,64). Tail: clear flags for next replay.
// ---------------------------------------------------------------------------

#define MAXE   131072
#define HD     256
#define NCOUNT 4097
#define BE     64
#define ASTRH  264              // A row stride in halves

__device__ int g_counts[MAXE];
__device__ int g_flags[NCOUNT];
__device__ int g_vals[NCOUNT];
__device__ int g_nvals;
__device__ int g_arrive;
__device__ __align__(16) float    g_table[NCOUNT * HD];
__device__ __align__(16) float    g_h2[NCOUNT * HD];
__device__ __align__(16) uint32_t g_whf[3 * HD * HD / 2];  // permuted fp16 W

// ---------------- SMEM layout (dynamic, per CTA) ----------------
#define ACT_OFF   0                        // 64 x 264 halves = 33792 B
#define WB_OFF    33792                    // 4 pairs x 4 bufs x 4KB = 65536 B
#define BIAS_OFF  (WB_OFF + 65536)         // 99328: [b1|b2|lb1|lw2] f32
#define SMEM_SZ   (BIAS_OFF + 4096)        // 103424

// ---------------- PTX helpers ----------------
__device__ __forceinline__ uint32_t smem_u32(const void* p) {
    uint32_t a;
    asm("{ .reg .u64 t; cvta.to.shared.u64 t, %1; cvt.u32.u64 %0, t; }"
        : "=r"(a) : "l"(p));
    return a;
}
__device__ __forceinline__ void mma16(float* c, const uint32_t* a,
                                      uint32_t b0, uint32_t b1) {
    asm volatile(
        "mma.sync.aligned.m16n8k16.row.col.f32.f16.f16.f32 "
        "{%0,%1,%2,%3}, {%4,%5,%6,%7}, {%8,%9}, {%0,%1,%2,%3};"
        : "+f"(c[0]), "+f"(c[1]), "+f"(c[2]), "+f"(c[3])
        : "r"(a[0]), "r"(a[1]), "r"(a[2]), "r"(a[3]), "r"(b0), "r"(b1));
}
__device__ __forceinline__ void ldmx4(uint32_t* v, uint32_t addr) {
    asm volatile("ldmatrix.sync.aligned.m8n8.x4.shared.b16 {%0,%1,%2,%3}, [%4];"
                 : "=r"(v[0]), "=r"(v[1]), "=r"(v[2]), "=r"(v[3]) : "r"(addr));
}
__device__ __forceinline__ void lds128(uint32_t* v, uint32_t addr) {
    asm volatile("ld.shared.v4.b32 {%0,%1,%2,%3}, [%4];"
                 : "=r"(v[0]), "=r"(v[1]), "=r"(v[2]), "=r"(v[3]) : "r"(addr));
}
__device__ __forceinline__ void sts32(uint32_t addr, uint32_t v) {
    asm volatile("st.shared.b32 [%0], %1;" :: "r"(addr), "r"(v));
}
__device__ __forceinline__ void sts128(uint32_t addr, uint32_t v0, uint32_t v1,
                                       uint32_t v2, uint32_t v3) {
    asm volatile("st.shared.v4.b32 [%0], {%1,%2,%3,%4};"
                 :: "r"(addr), "r"(v0), "r"(v1), "r"(v2), "r"(v3));
}
__device__ __forceinline__ uint32_t h2u(float lo, float hi) {
    __half2 h = __floats2half2_rn(lo, hi);
    return *(uint32_t*)&h;
}
#define CP_ASYNC16(dst, src) \
    asm volatile("cp.async.cg.shared.global [%0], [%1], 16;" :: "r"(dst), "l"(src))
#define CP_COMMIT() asm volatile("cp.async.commit_group;" ::: "memory")
#define CP_WAIT(n)  asm volatile("cp.async.wait_group %0;" :: "n"(n) : "memory")
#define BAR_PAIR(id) \
    asm volatile("bar.sync %0, 64;" :: "r"(id) : "memory")

// exact # of elements in sorted arr[0..63] that are (LE ? <= v : < v).
// Descent step-sum is 63 -> returns min(c,63); final probe extends to 64:
// if unsaturated, arr[lo] fails the predicate (it is the first non-member);
// if saturated (c==64), arr[63] passes and lo becomes 64.
template <int LE>
__device__ __forceinline__ int count_bound(const int* __restrict__ arr, int v) {
    int lo = 0;
#pragma unroll
    for (int step = 32; step >= 1; step >>= 1) {
        int e = arr[lo + step - 1];
        bool go = LE ? (e <= v) : (e < v);
        lo += go ? step : 0;
    }
    int e = arr[lo];                        // lo in [0,63], safe
    lo += (LE ? (e <= v) : (e < v)) ? 1 : 0;
    return lo;
}

// ---------------- k0: fused wprep + cn_count ----------------
#define WPREP_BLOCKS 384       // 384*256 = 98304 = 3*HD*HD/2
__global__ void prep_kernel(const float* __restrict__ w0,
                            const float* __restrict__ w1,
                            const float* __restrict__ w2,
                            const int* __restrict__ nbr,
                            const int* __restrict__ tar, int E) {
    if (blockIdx.x < WPREP_BLOCKS) {
        int i = blockIdx.x * 256 + threadIdx.x;
        int j    = i & 3;
        int lane = (i >> 2) & 31;
        int ntw  = (i >> 7) & 3;
        int ks   = (i >> 9) & 1;
        int wn   = (i >> 10) & 3;
        int p    = (i >> 12) & 7;
        int mat  = i >> 15;
        int nt = 2 * (wn * 4 + ntw) + (j >> 1);
        int n  = nt * 8 + (lane >> 2);
        int k  = p * 32 + ks * 16 + (j & 1) * 8 + (lane & 3) * 2;
        const float* w = (mat == 0) ? w0 : (mat == 1) ? w1 : w2;
        g_whf[i] = h2u(w[k * HD + n], w[(k + 1) * HD + n]);
        return;
    }
    // ---- cn_count: warp per edge, binary-search counting ----
    __shared__ int s_b[8][64];
    int wid  = (blockIdx.x - WPREP_BLOCKS) * 8 + (threadIdx.x >> 5);
    int wloc = (threadIdx.x >> 5) & 7;
    int lane = threadIdx.x & 31;
    if (wid >= E) return;
    int s = tar[wid];
    int d = tar[E + wid];
    int2 a = ((const int2*)(nbr + (size_t)s * 64))[lane];
    int2 b = ((const int2*)(nbr + (size_t)d * 64))[lane];
    ((int2*)s_b[wloc])[lane] = b;
    __syncwarp();
    const int* arr = s_b[wloc];
    int cnt = count_bound<1>(arr, a.x) - count_bound<0>(arr, a.x)
            + count_bound<1>(arr, a.y) - count_bound<0>(arr, a.y);
#pragma unroll
    for (int off = 16; off; off >>= 1)
        cnt += __shfl_xor_sync(0xffffffffu, cnt, off);
    if (lane == 0) {
        g_counts[wid] = cnt;
        if (atomicExch(&g_flags[cnt], 1) == 0) {
            int idx = atomicAdd(&g_nvals, 1);
            g_vals[idx] = cnt;
        }
    }
}

// ---------------- k1: fused table (l2 + spin barrier + l3) ----------------
__global__ void table_kernel(const float* __restrict__ w1, const float* __restrict__ b1,
                             const float* __restrict__ w2, const float* __restrict__ b2,
                             const float* __restrict__ w3, const float* __restrict__ b3) {
    __shared__ float s_w1[HD], s_b1[HD];
    __shared__ float red[8][33];
    __shared__ float s_h2[HD];
    int tx = threadIdx.x, lane = tx & 31, wk = tx >> 5;
    int h = blockIdx.x * 32 + lane;
    for (int i = tx; i < HD; i += 256) { s_w1[i] = w1[i]; s_b1[i] = b1[i]; }
    float wr2[32], wr3[32];
#pragma unroll 8
    for (int kk = 0; kk < 32; ++kk) {
        wr2[kk] = w2[(wk * 32 + kk) * HD + h];
        wr3[kk] = w3[(wk * 32 + kk) * HD + h];
    }
    __syncthreads();
    int nv = g_nvals;
    float b2v = b2[h], b3v = b3[h];

    // phase 1: h2 = relu(relu(c*w1+b1) @ w2 + b2)
    for (int i = 0; i < nv; ++i) {
        float cf = (float)g_vals[i];
        float p = 0.f;
#pragma unroll 8
        for (int kk = 0; kk < 32; ++kk) {
            int k = wk * 32 + kk;
            p = fmaf(fmaxf(fmaf(cf, s_w1[k], s_b1[k]), 0.f), wr2[kk], p);
        }
        red[wk][lane] = p;
        __syncthreads();
        if (wk == 0) {
            float s = b2v;
#pragma unroll
            for (int j = 0; j < 8; ++j) s += red[j][lane];
            g_h2[i * HD + h] = fmaxf(s, 0.f);
        }
        __syncthreads();
    }

    // grid spin barrier (8 blocks, all co-resident)
    __threadfence();
    __syncthreads();
    if (tx == 0) {
        atomicAdd(&g_arrive, 1);
        while (atomicAdd(&g_arrive, 0) < 8) { }
        __threadfence();
    }
    __syncthreads();

    // phase 2: table[c] = h2 @ w3 + b3
    for (int i = 0; i < nv; ++i) {
        for (int j = tx; j < HD; j += 256) s_h2[j] = __ldcg(&g_h2[i * HD + j]);
        __syncthreads();
        float p = 0.f;
#pragma unroll 8
        for (int kk = 0; kk < 32; ++kk)
            p = fmaf(s_h2[wk * 32 + kk], wr3[kk], p);
        red[wk][lane] = p;
        __syncthreads();
        if (wk == 0) {
            float s = b3v;
#pragma unroll
            for (int j = 0; j < 8; ++j) s += red[j][lane];
            g_table[g_vals[i] * HD + h] = s;
        }
        __syncthreads();
    }
}

// ---------------- main kernel ----------------
// issue this warp's half (2KB) of pair wn's piece t into ring buffer t&3
__device__ __forceinline__ void issue_piece(uint32_t sb, int t, int wn, int wm,
                                            int lane) {
    const uint32_t* src = g_whf + ((((size_t)t * 4 + wn) * 2 + wm) << 9) + lane * 4;
    uint32_t dst = sb + WB_OFF + wn * 16384 + (t & 3) * 4096 + wm * 2048 + lane * 16;
#pragma unroll
    for (int it = 0; it < 4; ++it)
        CP_ASYNC16(dst + it * 512, src + it * 128);
    CP_COMMIT();
}

template <int RELU, int TAB>
__device__ __forceinline__ void epilogue(uint32_t sb, float acc[2][8][4],
                                         const float* __restrict__ bias,
                                         const int* __restrict__ s_tbl,
                                         float beta, int wm, int wn, int lane) {
    int q = lane & 3, gid = lane >> 2;
#pragma unroll
    for (int mt = 0; mt < 2; ++mt) {
        int r0 = wm * 32 + mt * 16 + gid;
        int trow0 = 0, trow1 = 0;
        if (TAB) { trow0 = s_tbl[r0]; trow1 = s_tbl[r0 + 8]; }
#pragma unroll
        for (int nt = 0; nt < 8; ++nt) {
            int colb = wn * 64 + nt * 8 + 2 * q;
            float2 bv = *(const float2*)(bias + colb);
            float v0 = acc[mt][nt][0] + bv.x;
            float v1 = acc[mt][nt][1] + bv.y;
            float v2 = acc[mt][nt][2] + bv.x;
            float v3 = acc[mt][nt][3] + bv.y;
            if (TAB) {
                float2 t0 = __ldg((const float2*)(g_table + trow0 + colb));
                float2 t1 = __ldg((const float2*)(g_table + trow1 + colb));
                v0 = fmaf(beta, t0.x, v0); v1 = fmaf(beta, t0.y, v1);
                v2 = fmaf(beta, t1.x, v2); v3 = fmaf(beta, t1.y, v3);
            }
            if (RELU) {
                v0 = fmaxf(v0, 0.f); v1 = fmaxf(v1, 0.f);
                v2 = fmaxf(v2, 0.f); v3 = fmaxf(v3, 0.f);
            }
            uint32_t a0 = sb + ACT_OFF + (uint32_t)(r0 * ASTRH + colb) * 2;
            sts32(a0, h2u(v0, v1));
            sts32(a0 + 8 * ASTRH * 2, h2u(v2, v3));
        }
    }
}

__global__ void __launch_bounds__(256, 2)
scn_mma_kernel(const float* __restrict__ x, const int* __restrict__ tar,
               const float* __restrict__ beta_p,
               const float* __restrict__ ijb1, const float* __restrict__ ijb2,
               const float* __restrict__ lb1,  const float* __restrict__ lw2,
               const float* __restrict__ lb2,  float* __restrict__ out, int E) {
    extern __shared__ char smem[];
    uint32_t sb = smem_u32(smem);
    int tx = threadIdx.x, w = tx >> 5, lane = tx & 31;
    int q = lane & 3, gid = lane >> 2;
    int wm = w & 1, wn = w >> 1;            // pair id = wn (threads 64*wn..+63)
    int e0 = blockIdx.x * BE;

    __shared__ int   s_src[BE], s_dst[BE], s_tbl[BE];
    __shared__ float s_red[BE];

    // prefetch first 3 pieces into the pair ring
    issue_piece(sb, 0, wn, wm, lane);
    issue_piece(sb, 1, wn, wm, lane);
    issue_piece(sb, 2, wn, wm, lane);

    float* sbias = (float*)(smem + BIAS_OFF);
    for (int i = tx; i < 1024; i += 256) {
        float v;
        if      (i < 256) v = ijb1[i];
        else if (i < 512) v = ijb2[i - 256];
        else if (i < 768) v = lb1[i - 512];
        else              v = lw2[i - 768];
        sbias[i] = v;
    }
    if (tx < BE) {
        int e = e0 + tx; if (e >= E) e = E - 1;
        s_src[tx] = tar[e];
        s_dst[tx] = tar[E + e];
        s_tbl[tx] = g_counts[e] * HD;
        s_red[tx] = 0.f;
    }
    __syncthreads();            // s_src/s_dst/s_tbl visible to all warps

    float beta = *beta_p;
    float lb2v = *lb2;

    // ---- gather: A = fp16(xi * xj), row-major stride ASTRH ----
#pragma unroll 4
    for (int it = 0; it < 8; ++it) {
        int i = it * 256 + tx;              // 2048 8-half slots
        int m = i >> 5, c8 = i & 31;
        const float4* xa = (const float4*)(x + (size_t)s_src[m] * HD);
        const float4* xb = (const float4*)(x + (size_t)s_dst[m] * HD);
        float4 a0 = xa[2 * c8],     b0 = xb[2 * c8];
        float4 a1 = xa[2 * c8 + 1], b1 = xb[2 * c8 + 1];
        sts128(sb + ACT_OFF + (uint32_t)(m * ASTRH + c8 * 8) * 2,
               h2u(a0.x * b0.x, a0.y * b0.y), h2u(a0.z * b0.z, a0.w * b0.w),
               h2u(a1.x * b1.x, a1.y * b1.y), h2u(a1.z * b1.z, a1.w * b1.w));
    }
    __syncthreads();

    // ldmatrix lane base
    uint32_t arow = (uint32_t)(wm * 32 + (lane & 7) + 8 * ((lane >> 3) & 1));
    uint32_t abase = sb + ACT_OFF + (arow * ASTRH + 8 * (uint32_t)(lane >> 4)) * 2;
    uint32_t wpair = sb + WB_OFF + wn * 16384;

    float acc[2][8][4];

#pragma unroll 1
    for (int t = 0; t < 24; ++t) {
        int c = t & 7, g = t >> 3;
        if (t < 22)      { CP_WAIT(2); }    // my half of piece t landed
        else if (t < 23) { CP_WAIT(1); }
        else             { CP_WAIT(0); }
        BAR_PAIR(wn + 1);                   // partner's half landed
        if (c == 0) {
#pragma unroll
            for (int mt = 0; mt < 2; ++mt)
#pragma unroll
                for (int nt = 0; nt < 8; ++nt)
#pragma unroll
                    for (int i = 0; i < 4; ++i) acc[mt][nt][i] = 0.f;
        }

        uint32_t bbuf = wpair + (uint32_t)(t & 3) * 4096;
#pragma unroll
        for (int ks = 0; ks < 2; ++ks) {
            int kst = c * 2 + ks;
            uint32_t a[2][4];
#pragma unroll
            for (int mt = 0; mt < 2; ++mt)
                ldmx4(a[mt], abase + (uint32_t)(mt * 16 * ASTRH + kst * 16) * 2);
            uint32_t bv[4][4];
            uint32_t bks = bbuf + ks * 2048 + lane * 16;
#pragma unroll
            for (int p = 0; p < 4; ++p)
                lds128(bv[p], bks + (uint32_t)(p * 512));
#pragma unroll
            for (int mt = 0; mt < 2; ++mt)
#pragma unroll
                for (int p = 0; p < 4; ++p) {
                    mma16(acc[mt][2 * p],     a[mt], bv[p][0], bv[p][1]);
                    mma16(acc[mt][2 * p + 1], a[mt], bv[p][2], bv[p][3]);
                }
        }

        if (t + 3 < 24) issue_piece(sb, t + 3, wn, wm, lane);

        if (c == 7) {
            __syncthreads();                // all warps done reading ACT
            if (g == 0) {
                epilogue<1, 0>(sb, acc, sbias,       s_tbl, beta, wm, wn, lane);
            } else if (g == 1) {
                epilogue<0, 1>(sb, acc, sbias + 256, s_tbl, beta, wm, wn, lane);
            } else {
                // final: out = relu(C + lb1) . lw2 + lb2
#pragma unroll
                for (int mt = 0; mt < 2; ++mt) {
                    float p0 = 0.f, p1 = 0.f;
#pragma unroll
                    for (int nt = 0; nt < 8; ++nt) {
                        int colb = wn * 64 + nt * 8 + 2 * q;
                        float2 lb = *(const float2*)(sbias + 512 + colb);
                        float2 lw = *(const float2*)(sbias + 768 + colb);
                        p0 = fmaf(fmaxf(acc[mt][nt][0] + lb.x, 0.f), lw.x, p0);
                        p0 = fmaf(fmaxf(acc[mt][nt][1] + lb.y, 0.f), lw.y, p0);
                        p1 = fmaf(fmaxf(acc[mt][nt][2] + lb.x, 0.f), lw.x, p1);
                        p1 = fmaf(fmaxf(acc[mt][nt][3] + lb.y, 0.f), lw.y, p1);
                    }
                    p0 += __shfl_xor_sync(0xffffffffu, p0, 1);
                    p0 += __shfl_xor_sync(0xffffffffu, p0, 2);
                    p1 += __shfl_xor_sync(0xffffffffu, p1, 1);
                    p1 += __shfl_xor_sync(0xffffffffu, p1, 2);
                    if (q == 0) {
                        int r0 = wm * 32 + mt * 16 + gid;
                        atomicAdd(&s_red[r0],     p0);
                        atomicAdd(&s_red[r0 + 8], p1);
                    }
                }
            }
            __syncthreads();                // epilogue writes visible
        }
    }

    if (tx < BE && e0 + tx < E) out[e0 + tx] = s_red[tx] + lb2v;

    // tail: clean global state for the next replay (globals start zeroed)
    if (blockIdx.x == 0) {
        for (int i = tx; i < NCOUNT; i += 256) g_flags[i] = 0;
        if (tx == 0) { g_nvals = 0; g_arrive = 0; }
    }
}

// ---------------------------------------------------------------------------
extern "C" void kernel_launch(void* const* d_in, const int* in_sizes, int n_in,
                              void* d_out, int out_size) {
    const float* x    = (const float*)d_in[0];
    const int*   nbr  = (const int*)d_in[1];
    const int*   tar  = (const int*)d_in[2];
    const float* beta = (const float*)d_in[3];
    const float* cw1  = (const float*)d_in[4];
    const float* cb1  = (const float*)d_in[5];
    const float* cw2  = (const float*)d_in[6];
    const float* cb2  = (const float*)d_in[7];
    const float* cw3  = (const float*)d_in[8];
    const float* cb3  = (const float*)d_in[9];
    const float* ijw1 = (const float*)d_in[10];
    const float* ijb1 = (const float*)d_in[11];
    const float* ijw2 = (const float*)d_in[12];
    const float* ijb2 = (const float*)d_in[13];
    const float* lw1  = (const float*)d_in[14];
    const float* lb1  = (const float*)d_in[15];
    const float* lw2  = (const float*)d_in[16];
    const float* lb2  = (const float*)d_in[17];
    float* out = (float*)d_out;

    int E = in_sizes[2] / 2;
    if (E > MAXE) E = MAXE;

    cudaFuncSetAttribute(scn_mma_kernel,
                         cudaFuncAttributeMaxDynamicSharedMemorySize, SMEM_SZ);

    int cn_blocks = (E + 7) / 8;
    prep_kernel<<<WPREP_BLOCKS + cn_blocks, 256>>>(ijw1, ijw2, lw1, nbr, tar, E);
    table_kernel<<<8, 256>>>(cw1, cb1, cw2, cb2, cw3, cb3);
    scn_mma_kernel<<<(E + BE - 1) / BE, 256, SMEM_SZ>>>(
        x, tar, beta, ijb1, ijb2, lb1, lw2, lb2, out, E);
}

// round 15
// speedup vs baseline: 1.3981x; 1.3981x over previous
#include <cuda_runtime.h>
#include <cuda_fp16.h>
#include <cuda_bf16.h>
#include <cstdint>

// ---------------------------------------------------------------------------
// SCNLinkPredictor — fp16 mma.sync m16n8k16, BE=64, 2 CTAs/SM,
// per-warp-pair weight rings. R15: CN count via two-level block search
// (8 register-resident boundaries -> parallel compares -> one 8-elem block
// probe per bound). Chain depth ~2 vs the 13-deep serial search of R14.
//
//  k0: fused [weight permute->fp16 | CN counts + compaction]
//  k1: fused CN-MLP table (layer2 + spin-barrier + layer3), 8 blocks
//  k2: main: 64 edges/CTA, 8 warps (2M x 4N). A row-major fp16 (stride 264).
//      B streamed per warp-pair: 4-deep 4KB ring, cp.async.wait_group +
//      bar.sync(pair,64). Tail: clear flags for next replay.
// ---------------------------------------------------------------------------

#define MAXE   131072
#define HD     256
#define NCOUNT 4097
#define BE     64
#define ASTRH  264              // A row stride in halves

__device__ int g_counts[MAXE];
__device__ int g_flags[NCOUNT];
__device__ int g_vals[NCOUNT];
__device__ int g_nvals;
__device__ int g_arrive;
__device__ __align__(16) float    g_table[NCOUNT * HD];
__device__ __align__(16) float    g_h2[NCOUNT * HD];
__device__ __align__(16) uint32_t g_whf[3 * HD * HD / 2];  // permuted fp16 W

// ---------------- SMEM layout (dynamic, per CTA) ----------------
#define ACT_OFF   0                        // 64 x 264 halves = 33792 B
#define WB_OFF    33792                    // 4 pairs x 4 bufs x 4KB = 65536 B
#define BIAS_OFF  (WB_OFF + 65536)         // 99328: [b1|b2|lb1|lw2] f32
#define SMEM_SZ   (BIAS_OFF + 4096)        // 103424

// ---------------- PTX helpers ----------------
__device__ __forceinline__ uint32_t smem_u32(const void* p) {
    uint32_t a;
    asm("{ .reg .u64 t; cvta.to.shared.u64 t, %1; cvt.u32.u64 %0, t; }"
        : "=r"(a) : "l"(p));
    return a;
}
__device__ __forceinline__ void mma16(float* c, const uint32_t* a,
                                      uint32_t b0, uint32_t b1) {
    asm volatile(
        "mma.sync.aligned.m16n8k16.row.col.f32.f16.f16.f32 "
        "{%0,%1,%2,%3}, {%4,%5,%6,%7}, {%8,%9}, {%0,%1,%2,%3};"
        : "+f"(c[0]), "+f"(c[1]), "+f"(c[2]), "+f"(c[3])
        : "r"(a[0]), "r"(a[1]), "r"(a[2]), "r"(a[3]), "r"(b0), "r"(b1));
}
__device__ __forceinline__ void ldmx4(uint32_t* v, uint32_t addr) {
    asm volatile("ldmatrix.sync.aligned.m8n8.x4.shared.b16 {%0,%1,%2,%3}, [%4];"
                 : "=r"(v[0]), "=r"(v[1]), "=r"(v[2]), "=r"(v[3]) : "r"(addr));
}
__device__ __forceinline__ void lds128(uint32_t* v, uint32_t addr) {
    asm volatile("ld.shared.v4.b32 {%0,%1,%2,%3}, [%4];"
                 : "=r"(v[0]), "=r"(v[1]), "=r"(v[2]), "=r"(v[3]) : "r"(addr));
}
__device__ __forceinline__ void sts32(uint32_t addr, uint32_t v) {
    asm volatile("st.shared.b32 [%0], %1;" :: "r"(addr), "r"(v));
}
__device__ __forceinline__ void sts128(uint32_t addr, uint32_t v0, uint32_t v1,
                                       uint32_t v2, uint32_t v3) {
    asm volatile("st.shared.v4.b32 [%0], {%1,%2,%3,%4};"
                 :: "r"(addr), "r"(v0), "r"(v1), "r"(v2), "r"(v3));
}
__device__ __forceinline__ uint32_t h2u(float lo, float hi) {
    __half2 h = __floats2half2_rn(lo, hi);
    return *(uint32_t*)&h;
}
#define CP_ASYNC16(dst, src) \
    asm volatile("cp.async.cg.shared.global [%0], [%1], 16;" :: "r"(dst), "l"(src))
#define CP_COMMIT() asm volatile("cp.async.commit_group;" ::: "memory")
#define CP_WAIT(n)  asm volatile("cp.async.wait_group %0;" :: "n"(n) : "memory")
#define BAR_PAIR(id) \
    asm volatile("bar.sync %0, 64;" :: "r"(id) : "memory")

// Exact multiplicity of v in sorted arr[0..63] via two-level block search.
// bd[j] = arr[8j+7] (block boundaries, register-resident).
// cntLT = #elems < v: F_LT full blocks + in-block probe; cntLE analogous.
__device__ __forceinline__ int cn_multiplicity(const int* __restrict__ arr,
                                               const int bd[8], int v) {
    int FLT = 0, FLE = 0;
#pragma unroll
    for (int j = 0; j < 8; ++j) {
        FLT += (bd[j] < v)  ? 1 : 0;
        FLE += (bd[j] <= v) ? 1 : 0;
    }
    // cntLT
    int fc = FLT < 7 ? FLT : 7;
    int4 p0 = ((const int4*)arr)[2 * fc];
    int4 p1 = ((const int4*)arr)[2 * fc + 1];
    int s = (p0.x < v) + (p0.y < v) + (p0.z < v) + (p0.w < v)
          + (p1.x < v) + (p1.y < v) + (p1.z < v) + (p1.w < v);
    int cLT = (FLT == 8) ? 64 : (8 * FLT + s);
    // cntLE
    int fe = FLE < 7 ? FLE : 7;
    int4 q0 = ((const int4*)arr)[2 * fe];
    int4 q1 = ((const int4*)arr)[2 * fe + 1];
    int t = (q0.x <= v) + (q0.y <= v) + (q0.z <= v) + (q0.w <= v)
          + (q1.x <= v) + (q1.y <= v) + (q1.z <= v) + (q1.w <= v);
    int cLE = (FLE == 8) ? 64 : (8 * FLE + t);
    return cLE - cLT;
}

// ---------------- k0: fused wprep + cn_count ----------------
#define WPREP_BLOCKS 384       // 384*256 = 98304 = 3*HD*HD/2
__global__ void prep_kernel(const float* __restrict__ w0,
                            const float* __restrict__ w1,
                            const float* __restrict__ w2,
                            const int* __restrict__ nbr,
                            const int* __restrict__ tar, int E) {
    if (blockIdx.x < WPREP_BLOCKS) {
        int i = blockIdx.x * 256 + threadIdx.x;
        int j    = i & 3;
        int lane = (i >> 2) & 31;
        int ntw  = (i >> 7) & 3;
        int ks   = (i >> 9) & 1;
        int wn   = (i >> 10) & 3;
        int p    = (i >> 12) & 7;
        int mat  = i >> 15;
        int nt = 2 * (wn * 4 + ntw) + (j >> 1);
        int n  = nt * 8 + (lane >> 2);
        int k  = p * 32 + ks * 16 + (j & 1) * 8 + (lane & 3) * 2;
        const float* w = (mat == 0) ? w0 : (mat == 1) ? w1 : w2;
        g_whf[i] = h2u(w[k * HD + n], w[(k + 1) * HD + n]);
        return;
    }
    // ---- cn_count: warp per edge, two-level block search ----
    __shared__ int s_b[8][64];
    int wid  = (blockIdx.x - WPREP_BLOCKS) * 8 + (threadIdx.x >> 5);
    int wloc = (threadIdx.x >> 5) & 7;
    int lane = threadIdx.x & 31;
    if (wid >= E) return;
    int s = tar[wid];
    int d = tar[E + wid];
    int2 a = ((const int2*)(nbr + (size_t)s * 64))[lane];
    int2 b = ((const int2*)(nbr + (size_t)d * 64))[lane];
    ((int2*)s_b[wloc])[lane] = b;
    __syncwarp();
    const int* arr = s_b[wloc];
    int bd[8];
#pragma unroll
    for (int j = 0; j < 8; ++j) bd[j] = arr[8 * j + 7];   // uniform broadcast
    int cnt = cn_multiplicity(arr, bd, a.x)
            + cn_multiplicity(arr, bd, a.y);
#pragma unroll
    for (int off = 16; off; off >>= 1)
        cnt += __shfl_xor_sync(0xffffffffu, cnt, off);
    if (lane == 0) {
        g_counts[wid] = cnt;
        if (atomicExch(&g_flags[cnt], 1) == 0) {
            int idx = atomicAdd(&g_nvals, 1);
            g_vals[idx] = cnt;
        }
    }
}

// ---------------- k1: fused table (l2 + spin barrier + l3) ----------------
__global__ void table_kernel(const float* __restrict__ w1, const float* __restrict__ b1,
                             const float* __restrict__ w2, const float* __restrict__ b2,
                             const float* __restrict__ w3, const float* __restrict__ b3) {
    __shared__ float s_w1[HD], s_b1[HD];
    __shared__ float red[8][33];
    __shared__ float s_h2[HD];
    int tx = threadIdx.x, lane = tx & 31, wk = tx >> 5;
    int h = blockIdx.x * 32 + lane;
    for (int i = tx; i < HD; i += 256) { s_w1[i] = w1[i]; s_b1[i] = b1[i]; }
    float wr2[32], wr3[32];
#pragma unroll 8
    for (int kk = 0; kk < 32; ++kk) {
        wr2[kk] = w2[(wk * 32 + kk) * HD + h];
        wr3[kk] = w3[(wk * 32 + kk) * HD + h];
    }
    __syncthreads();
    int nv = g_nvals;
    float b2v = b2[h], b3v = b3[h];

    // phase 1: h2 = relu(relu(c*w1+b1) @ w2 + b2)
    for (int i = 0; i < nv; ++i) {
        float cf = (float)g_vals[i];
        float p = 0.f;
#pragma unroll 8
        for (int kk = 0; kk < 32; ++kk) {
            int k = wk * 32 + kk;
            p = fmaf(fmaxf(fmaf(cf, s_w1[k], s_b1[k]), 0.f), wr2[kk], p);
        }
        red[wk][lane] = p;
        __syncthreads();
        if (wk == 0) {
            float s = b2v;
#pragma unroll
            for (int j = 0; j < 8; ++j) s += red[j][lane];
            g_h2[i * HD + h] = fmaxf(s, 0.f);
        }
        __syncthreads();
    }

    // grid spin barrier (8 blocks, all co-resident)
    __threadfence();
    __syncthreads();
    if (tx == 0) {
        atomicAdd(&g_arrive, 1);
        while (atomicAdd(&g_arrive, 0) < 8) { }
        __threadfence();
    }
    __syncthreads();

    // phase 2: table[c] = h2 @ w3 + b3
    for (int i = 0; i < nv; ++i) {
        for (int j = tx; j < HD; j += 256) s_h2[j] = __ldcg(&g_h2[i * HD + j]);
        __syncthreads();
        float p = 0.f;
#pragma unroll 8
        for (int kk = 0; kk < 32; ++kk)
            p = fmaf(s_h2[wk * 32 + kk], wr3[kk], p);
        red[wk][lane] = p;
        __syncthreads();
        if (wk == 0) {
            float s = b3v;
#pragma unroll
            for (int j = 0; j < 8; ++j) s += red[j][lane];
            g_table[g_vals[i] * HD + h] = s;
        }
        __syncthreads();
    }
}

// ---------------- main kernel ----------------
// issue this warp's half (2KB) of pair wn's piece t into ring buffer t&3
__device__ __forceinline__ void issue_piece(uint32_t sb, int t, int wn, int wm,
                                            int lane) {
    const uint32_t* src = g_whf + ((((size_t)t * 4 + wn) * 2 + wm) << 9) + lane * 4;
    uint32_t dst = sb + WB_OFF + wn * 16384 + (t & 3) * 4096 + wm * 2048 + lane * 16;
#pragma unroll
    for (int it = 0; it < 4; ++it)
        CP_ASYNC16(dst + it * 512, src + it * 128);
    CP_COMMIT();
}

template <int RELU, int TAB>
__device__ __forceinline__ void epilogue(uint32_t sb, float acc[2][8][4],
                                         const float* __restrict__ bias,
                                         const int* __restrict__ s_tbl,
                                         float beta, int wm, int wn, int lane) {
    int q = lane & 3, gid = lane >> 2;
#pragma unroll
    for (int mt = 0; mt < 2; ++mt) {
        int r0 = wm * 32 + mt * 16 + gid;
        int trow0 = 0, trow1 = 0;
        if (TAB) { trow0 = s_tbl[r0]; trow1 = s_tbl[r0 + 8]; }
#pragma unroll
        for (int nt = 0; nt < 8; ++nt) {
            int colb = wn * 64 + nt * 8 + 2 * q;
            float2 bv = *(const float2*)(bias + colb);
            float v0 = acc[mt][nt][0] + bv.x;
            float v1 = acc[mt][nt][1] + bv.y;
            float v2 = acc[mt][nt][2] + bv.x;
            float v3 = acc[mt][nt][3] + bv.y;
            if (TAB) {
                float2 t0 = __ldg((const float2*)(g_table + trow0 + colb));
                float2 t1 = __ldg((const float2*)(g_table + trow1 + colb));
                v0 = fmaf(beta, t0.x, v0); v1 = fmaf(beta, t0.y, v1);
                v2 = fmaf(beta, t1.x, v2); v3 = fmaf(beta, t1.y, v3);
            }
            if (RELU) {
                v0 = fmaxf(v0, 0.f); v1 = fmaxf(v1, 0.f);
                v2 = fmaxf(v2, 0.f); v3 = fmaxf(v3, 0.f);
            }
            uint32_t a0 = sb + ACT_OFF + (uint32_t)(r0 * ASTRH + colb) * 2;
            sts32(a0, h2u(v0, v1));
            sts32(a0 + 8 * ASTRH * 2, h2u(v2, v3));
        }
    }
}

__global__ void __launch_bounds__(256, 2)
scn_mma_kernel(const float* __restrict__ x, const int* __restrict__ tar,
               const float* __restrict__ beta_p,
               const float* __restrict__ ijb1, const float* __restrict__ ijb2,
               const float* __restrict__ lb1,  const float* __restrict__ lw2,
               const float* __restrict__ lb2,  float* __restrict__ out, int E) {
    extern __shared__ char smem[];
    uint32_t sb = smem_u32(smem);
    int tx = threadIdx.x, w = tx >> 5, lane = tx & 31;
    int q = lane & 3, gid = lane >> 2;
    int wm = w & 1, wn = w >> 1;            // pair id = wn (threads 64*wn..+63)
    int e0 = blockIdx.x * BE;

    __shared__ int   s_src[BE], s_dst[BE], s_tbl[BE];
    __shared__ float s_red[BE];

    // prefetch first 3 pieces into the pair ring
    issue_piece(sb, 0, wn, wm, lane);
    issue_piece(sb, 1, wn, wm, lane);
    issue_piece(sb, 2, wn, wm, lane);

    float* sbias = (float*)(smem + BIAS_OFF);
    for (int i = tx; i < 1024; i += 256) {
        float v;
        if      (i < 256) v = ijb1[i];
        else if (i < 512) v = ijb2[i - 256];
        else if (i < 768) v = lb1[i - 512];
        else              v = lw2[i - 768];
        sbias[i] = v;
    }
    if (tx < BE) {
        int e = e0 + tx; if (e >= E) e = E - 1;
        s_src[tx] = tar[e];
        s_dst[tx] = tar[E + e];
        s_tbl[tx] = g_counts[e] * HD;
        s_red[tx] = 0.f;
    }
    __syncthreads();            // s_src/s_dst/s_tbl visible to all warps

    float beta = *beta_p;
    float lb2v = *lb2;

    // ---- gather: A = fp16(xi * xj), row-major stride ASTRH ----
#pragma unroll 4
    for (int it = 0; it < 8; ++it) {
        int i = it * 256 + tx;              // 2048 8-half slots
        int m = i >> 5, c8 = i & 31;
        const float4* xa = (const float4*)(x + (size_t)s_src[m] * HD);
        const float4* xb = (const float4*)(x + (size_t)s_dst[m] * HD);
        float4 a0 = xa[2 * c8],     b0 = xb[2 * c8];
        float4 a1 = xa[2 * c8 + 1], b1 = xb[2 * c8 + 1];
        sts128(sb + ACT_OFF + (uint32_t)(m * ASTRH + c8 * 8) * 2,
               h2u(a0.x * b0.x, a0.y * b0.y), h2u(a0.z * b0.z, a0.w * b0.w),
               h2u(a1.x * b1.x, a1.y * b1.y), h2u(a1.z * b1.z, a1.w * b1.w));
    }
    __syncthreads();

    // ldmatrix lane base
    uint32_t arow = (uint32_t)(wm * 32 + (lane & 7) + 8 * ((lane >> 3) & 1));
    uint32_t abase = sb + ACT_OFF + (arow * ASTRH + 8 * (uint32_t)(lane >> 4)) * 2;
    uint32_t wpair = sb + WB_OFF + wn * 16384;

    float acc[2][8][4];

#pragma unroll 1
    for (int t = 0; t < 24; ++t) {
        int c = t & 7, g = t >> 3;
        if (t < 22)      { CP_WAIT(2); }    // my half of piece t landed
        else if (t < 23) { CP_WAIT(1); }
        else             { CP_WAIT(0); }
        BAR_PAIR(wn + 1);                   // partner's half landed
        if (c == 0) {
#pragma unroll
            for (int mt = 0; mt < 2; ++mt)
#pragma unroll
                for (int nt = 0; nt < 8; ++nt)
#pragma unroll
                    for (int i = 0; i < 4; ++i) acc[mt][nt][i] = 0.f;
        }

        uint32_t bbuf = wpair + (uint32_t)(t & 3) * 4096;
#pragma unroll
        for (int ks = 0; ks < 2; ++ks) {
            int kst = c * 2 + ks;
            uint32_t a[2][4];
#pragma unroll
            for (int mt = 0; mt < 2; ++mt)
                ldmx4(a[mt], abase + (uint32_t)(mt * 16 * ASTRH + kst * 16) * 2);
            uint32_t bv[4][4];
            uint32_t bks = bbuf + ks * 2048 + lane * 16;
#pragma unroll
            for (int p = 0; p < 4; ++p)
                lds128(bv[p], bks + (uint32_t)(p * 512));
#pragma unroll
            for (int mt = 0; mt < 2; ++mt)
#pragma unroll
                for (int p = 0; p < 4; ++p) {
                    mma16(acc[mt][2 * p],     a[mt], bv[p][0], bv[p][1]);
                    mma16(acc[mt][2 * p + 1], a[mt], bv[p][2], bv[p][3]);
                }
        }

        if (t + 3 < 24) issue_piece(sb, t + 3, wn, wm, lane);

        if (c == 7) {
            __syncthreads();                // all warps done reading ACT
            if (g == 0) {
                epilogue<1, 0>(sb, acc, sbias,       s_tbl, beta, wm, wn, lane);
            } else if (g == 1) {
                epilogue<0, 1>(sb, acc, sbias + 256, s_tbl, beta, wm, wn, lane);
            } else {
                // final: out = relu(C + lb1) . lw2 + lb2
#pragma unroll
                for (int mt = 0; mt < 2; ++mt) {
                    float p0 = 0.f, p1 = 0.f;
#pragma unroll
                    for (int nt = 0; nt < 8; ++nt) {
                        int colb = wn * 64 + nt * 8 + 2 * q;
                        float2 lb = *(const float2*)(sbias + 512 + colb);
                        float2 lw = *(const float2*)(sbias + 768 + colb);
                        p0 = fmaf(fmaxf(acc[mt][nt][0] + lb.x, 0.f), lw.x, p0);
                        p0 = fmaf(fmaxf(acc[mt][nt][1] + lb.y, 0.f), lw.y, p0);
                        p1 = fmaf(fmaxf(acc[mt][nt][2] + lb.x, 0.f), lw.x, p1);
                        p1 = fmaf(fmaxf(acc[mt][nt][3] + lb.y, 0.f), lw.y, p1);
                    }
                    p0 += __shfl_xor_sync(0xffffffffu, p0, 1);
                    p0 += __shfl_xor_sync(0xffffffffu, p0, 2);
                    p1 += __shfl_xor_sync(0xffffffffu, p1, 1);
                    p1 += __shfl_xor_sync(0xffffffffu, p1, 2);
                    if (q == 0) {
                        int r0 = wm * 32 + mt * 16 + gid;
                        atomicAdd(&s_red[r0],     p0);
                        atomicAdd(&s_red[r0 + 8], p1);
                    }
                }
            }
            __syncthreads();                // epilogue writes visible
        }
    }

    if (tx < BE && e0 + tx < E) out[e0 + tx] = s_red[tx] + lb2v;

    // tail: clean global state for the next replay (globals start zeroed)
    if (blockIdx.x == 0) {
        for (int i = tx; i < NCOUNT; i += 256) g_flags[i] = 0;
        if (tx == 0) { g_nvals = 0; g_arrive = 0; }
    }
}

// ---------------------------------------------------------------------------
extern "C" void kernel_launch(void* const* d_in, const int* in_sizes, int n_in,
                              void* d_out, int out_size) {
    const float* x    = (const float*)d_in[0];
    const int*   nbr  = (const int*)d_in[1];
    const int*   tar  = (const int*)d_in[2];
    const float* beta = (const float*)d_in[3];
    const float* cw1  = (const float*)d_in[4];
    const float* cb1  = (const float*)d_in[5];
    const float* cw2  = (const float*)d_in[6];
    const float* cb2  = (const float*)d_in[7];
    const float* cw3  = (const float*)d_in[8];
    const float* cb3  = (const float*)d_in[9];
    const float* ijw1 = (const float*)d_in[10];
    const float* ijb1 = (const float*)d_in[11];
    const float* ijw2 = (const float*)d_in[12];
    const float* ijb2 = (const float*)d_in[13];
    const float* lw1  = (const float*)d_in[14];
    const float* lb1  = (const float*)d_in[15];
    const float* lw2  = (const float*)d_in[16];
    const float* lb2  = (const float*)d_in[17];
    float* out = (float*)d_out;

    int E = in_sizes[2] / 2;
    if (E > MAXE) E = MAXE;

    cudaFuncSetAttribute(scn_mma_kernel,
                         cudaFuncAttributeMaxDynamicSharedMemorySize, SMEM_SZ);

    int cn_blocks = (E + 7) / 8;
    prep_kernel<<<WPREP_BLOCKS + cn_blocks, 256>>>(ijw1, ijw2, lw1, nbr, tar, E);
    table_kernel<<<8, 256>>>(cw1, cb1, cw2, cb2, cw3, cb3);
    scn_mma_kernel<<<(E + BE - 1) / BE, 256, SMEM_SZ>>>(
        x, tar, beta, ijb1, ijb2, lb1, lw2, lb2, out, E);
}